// round 4
// baseline (speedup 1.0000x reference)
#include <cuda_runtime.h>

// Problem constants
#define HH 256
#define WW 256
#define CC 64      // content/blur channels, also output channels of deform conv
#define BB 4
#define OC 18      // offset channels actually used
#define OCP 20     // padded to multiple of 4
#define HW (HH*WW)

typedef unsigned long long ull;

// ---------------------------------------------------------------------------
// f32x2 packed helpers (sm_103a FFMA2 path — only reachable via PTX)
// ---------------------------------------------------------------------------
__device__ __forceinline__ void ffma2(ull& d, ull a, ull b) {
    asm("fma.rn.f32x2 %0, %1, %2, %0;" : "+l"(d) : "l"(a), "l"(b));
}
__device__ __forceinline__ ull packf(float lo, float hi) {
    ull r; asm("mov.b64 %0, {%1, %2};" : "=l"(r) : "f"(lo), "f"(hi)); return r;
}
__device__ __forceinline__ ull packu(unsigned lo, unsigned hi) {
    ull r; asm("mov.b64 %0, {%1, %2};" : "=l"(r) : "r"(lo), "r"(hi)); return r;
}
__device__ __forceinline__ void unpackf(ull v, float& lo, float& hi) {
    asm("mov.b64 {%0, %1}, %2;" : "=f"(lo), "=f"(hi) : "l"(v));
}

// Duplicated deform weights: g_wdup[(k*64 + c)*64 + o] = {w, w} (f32x2)
__device__ ull g_wdup[9 * CC * CC];

// ---------------------------------------------------------------------------
// Prelude: transpose + duplicate dc_w (64,64,3,3) -> g_wdup[k][c][o] f32x2
// ---------------------------------------------------------------------------
__global__ void wdup_kernel(const float* __restrict__ dw)
{
    int idx = blockIdx.x * blockDim.x + threadIdx.x;   // 0 .. 9*64*64-1
    int o = idx & 63;
    int c = (idx >> 6) & 63;
    int k = idx >> 12;
    float w = __ldg(dw + (o * CC + c) * 9 + k);
    g_wdup[idx] = packf(w, w);
}

// ---------------------------------------------------------------------------
// Kernel A: 3x3 conv (pad 1): blur x offset_w -> offset (18 ch).
// One thread per pixel; 18(+2 pad) output channels as 10 f32x2 accumulators,
// packed over o-pairs (weights contiguous in smem -> natural pairs,
// input value duplicated once per (c,k)).
// ---------------------------------------------------------------------------
__global__ __launch_bounds__(256, 4)
void offset_conv_kernel(const float* __restrict__ blur,
                        const float* __restrict__ ow,   // (27,64,3,3)
                        const float* __restrict__ ob,   // (27,)
                        float* __restrict__ off_out)    // (4,18,256,256)
{
    __shared__ float ws[CC * 9 * OCP];   // [c][k][o_padded], 46,080 B

    const int tid = threadIdx.x;
    for (int i = tid; i < CC * 9 * OCP; i += blockDim.x) {
        int o  = i % OCP;
        int ck = i / OCP;
        ws[i] = (o < OC) ? ow[o * (CC * 9) + ck] : 0.0f;
    }
    __syncthreads();

    const int p = blockIdx.x * blockDim.x + tid;
    const int x = p & (WW - 1);
    const int y = (p >> 8) & (HH - 1);
    const int b = p >> 16;

    ull acc[OCP / 2];
#pragma unroll
    for (int j = 0; j < OCP / 2; j++) acc[j] = 0ull;

    const float* bp = blur + (size_t)b * CC * HW;

    for (int c = 0; c < CC; c++) {
        const float* cp = bp + c * HW;
#pragma unroll
        for (int k = 0; k < 9; k++) {
            const int iy = y + k / 3 - 1;
            const int ix = x + k % 3 - 1;
            float v = 0.0f;
            if (iy >= 0 && iy < HH && ix >= 0 && ix < WW)
                v = __ldg(cp + iy * WW + ix);
            const ull vv = packf(v, v);
            const uint4* w4 = reinterpret_cast<const uint4*>(ws + (c * 9 + k) * OCP);
#pragma unroll
            for (int j = 0; j < 5; j++) {
                uint4 t = w4[j];
                ffma2(acc[2 * j],     packu(t.x, t.y), vv);
                ffma2(acc[2 * j + 1], packu(t.z, t.w), vv);
            }
        }
    }

    float* op = off_out + ((size_t)b * OC) * HW + y * WW + x;
#pragma unroll
    for (int j = 0; j < 9; j++) {       // pairs 0..8 cover o = 0..17
        float a0, a1;
        unpackf(acc[j], a0, a1);
        op[(2 * j)     * HW] = a0 + __ldg(ob + 2 * j);
        op[(2 * j + 1) * HW] = a1 + __ldg(ob + 2 * j + 1);
    }
}

// ---------------------------------------------------------------------------
// Kernel B: deformable conv as a fused gather + tiled GEMM.
// Block = one row: tile 256 px x 64 out-ch, 256 threads.
// Per k: (1) gather phase: thread=pixel, bilinear-sample all 64 channels
//            into smem S[c][px] (64 KB);
//        (2) GEMM phase: thread = 8 px x 8 o, f32x2 packed over px-pairs.
//            Weights (pre-duplicated f32x2) read warp-uniform via L1.
// Warp layout in GEMM: lane l -> og = l&7, pg = (w<<2)|(l>>3): sample smem
// reads dedupe to 4 distinct 16B chunks/warp; weight reads 8 distinct
// 16B chunks/warp -> ~1 wavefront each.
// ---------------------------------------------------------------------------
__global__ __launch_bounds__(256, 2)
void deform_conv_kernel(const float* __restrict__ content,
                        const float* __restrict__ offset,  // (4,18,256,256)
                        const float* __restrict__ db,      // (64,)
                        float* __restrict__ out)           // (4,64,256,256)
{
    extern __shared__ float S[];        // [64][256] samples for current k, 64 KB

    const int tid  = threadIdx.x;
    const int b    = blockIdx.x >> 8;
    const int y    = blockIdx.x & 255;
    const int w    = tid >> 5;
    const int l    = tid & 31;
    const int og   = l & 7;             // o-group: o = og*8 .. og*8+7
    const int pg   = (w << 2) | (l >> 3); // px-group: px = pg*8 .. pg*8+7

    ull acc[8][4];                      // [oi][px-pair]
#pragma unroll
    for (int oi = 0; oi < 8; oi++)
#pragma unroll
        for (int pp = 0; pp < 4; pp++) acc[oi][pp] = 0ull;

    const float* cb   = content + (size_t)b * CC * HW;
    const float* offb = offset + (size_t)b * OC * HW + y * WW + tid;

    for (int k = 0; k < 9; k++) {
        __syncthreads();    // S from previous k fully consumed

        // ---- gather phase: this thread = pixel (y, x=tid) ----
        {
            const float offy = __ldg(offb + (2 * k) * HW);
            const float offx = __ldg(offb + (2 * k + 1) * HW);
            const float py = (float)(y + (k / 3) - 1) + offy;
            const float px = (float)(tid + (k % 3) - 1) + offx;

            const float y0f = floorf(py);
            const float x0f = floorf(px);
            const float wy = py - y0f;
            const float wx = px - x0f;
            const int iy0 = (int)y0f, ix0 = (int)x0f;
            const int iy1 = iy0 + 1,  ix1 = ix0 + 1;

            const bool vy0 = (iy0 >= 0) && (iy0 < HH);
            const bool vy1 = (iy1 >= 0) && (iy1 < HH);
            const bool vx0 = (ix0 >= 0) && (ix0 < WW);
            const bool vx1 = (ix1 >= 0) && (ix1 < WW);

            const float w00 = (1.f - wy) * (1.f - wx) * ((vy0 && vx0) ? 1.f : 0.f);
            const float w01 = (1.f - wy) * wx         * ((vy0 && vx1) ? 1.f : 0.f);
            const float w10 = wy * (1.f - wx)         * ((vy1 && vx0) ? 1.f : 0.f);
            const float w11 = wy * wx                 * ((vy1 && vx1) ? 1.f : 0.f);

            const int cy0 = min(max(iy0, 0), HH - 1);
            const int cy1 = min(max(iy1, 0), HH - 1);
            const int cx0 = min(max(ix0, 0), WW - 1);
            const int cx1 = min(max(ix1, 0), WW - 1);

            const float* p00 = cb + cy0 * WW + cx0;
            const float* p01 = cb + cy0 * WW + cx1;
            const float* p10 = cb + cy1 * WW + cx0;
            const float* p11 = cb + cy1 * WW + cx1;

#pragma unroll 4
            for (int c = 0; c < CC; c++) {
                const int co = c * HW;
                float samp = w00 * __ldg(p00 + co)
                           + w01 * __ldg(p01 + co)
                           + w10 * __ldg(p10 + co)
                           + w11 * __ldg(p11 + co);
                S[c * WW + tid] = samp;
            }
        }
        __syncthreads();

        // ---- GEMM phase: acc[o][px] += W[o,k,c] * S[c][px] ----
        const uint4* S4 = reinterpret_cast<const uint4*>(S);
        const uint4* W4 = reinterpret_cast<const uint4*>(g_wdup + (size_t)k * CC * CC);

#pragma unroll 2
        for (int c = 0; c < CC; c++) {
            // 8 px of this thread's px-group, as 4 f32x2 pairs
            uint4 s0 = S4[c * 64 + pg * 2];
            uint4 s1 = S4[c * 64 + pg * 2 + 1];
            ull sp[4];
            sp[0] = packu(s0.x, s0.y);
            sp[1] = packu(s0.z, s0.w);
            sp[2] = packu(s1.x, s1.y);
            sp[3] = packu(s1.z, s1.w);

            // 8 duplicated weights of this thread's o-group (warp-uniform, L1-hit)
            ull wq[8];
#pragma unroll
            for (int j = 0; j < 4; j++) {
                uint4 t = __ldg(W4 + c * 32 + og * 4 + j);
                wq[2 * j]     = packu(t.x, t.y);
                wq[2 * j + 1] = packu(t.z, t.w);
            }

#pragma unroll
            for (int oi = 0; oi < 8; oi++)
#pragma unroll
                for (int pp = 0; pp < 4; pp++)
                    ffma2(acc[oi][pp], wq[oi], sp[pp]);
        }
    }

    // ---- epilogue: 8 o x 8 px per thread, float4 stores ----
#pragma unroll
    for (int oi = 0; oi < 8; oi++) {
        const int o = og * 8 + oi;
        const float bias = __ldg(db + o);
        float* op = out + ((size_t)b * CC + o) * HW + y * WW + pg * 8;
        float a0, a1, a2, a3;
        unpackf(acc[oi][0], a0, a1);
        unpackf(acc[oi][1], a2, a3);
        reinterpret_cast<float4*>(op)[0] =
            make_float4(a0 + bias, a1 + bias, a2 + bias, a3 + bias);
        unpackf(acc[oi][2], a0, a1);
        unpackf(acc[oi][3], a2, a3);
        reinterpret_cast<float4*>(op)[1] =
            make_float4(a0 + bias, a1 + bias, a2 + bias, a3 + bias);
    }
}

// ---------------------------------------------------------------------------
// kernel_launch
//   d_in[0] content_feats (4,64,256,256) f32
//   d_in[1] blur_feats    (4,64,256,256) f32
//   d_in[2] offset_w      (27,64,3,3)    f32
//   d_in[3] offset_b      (27,)          f32
//   d_in[4] dc_w          (64,64,3,3)    f32
//   d_in[5] dc_b          (64,)          f32
// d_out = [ out (4,64,256,256) | offset (4,18,256,256) ]
// ---------------------------------------------------------------------------
extern "C" void kernel_launch(void* const* d_in, const int* in_sizes, int n_in,
                              void* d_out, int out_size)
{
    const float* content = (const float*)d_in[0];
    const float* blur    = (const float*)d_in[1];
    const float* ow      = (const float*)d_in[2];
    const float* ob      = (const float*)d_in[3];
    const float* dw      = (const float*)d_in[4];
    const float* db      = (const float*)d_in[5];

    float* out     = (float*)d_out;
    float* off_out = out + (size_t)BB * CC * HW;

    const int smem_deform = CC * WW * (int)sizeof(float);   // 64 KB
    cudaFuncSetAttribute(deform_conv_kernel,
                         cudaFuncAttributeMaxDynamicSharedMemorySize, smem_deform);

    wdup_kernel<<<(9 * CC * CC) / 256, 256>>>(dw);
    offset_conv_kernel<<<(BB * HW) / 256, 256>>>(blur, ow, ob, off_out);
    deform_conv_kernel<<<BB * HH, 256, smem_deform>>>(content, off_out, db, out);
}

// round 7
// speedup vs baseline: 1.4495x; 1.4495x over previous
#include <cuda_runtime.h>

// Problem constants
#define HH 256
#define WW 256
#define CC 64      // content/blur channels, also output channels of deform conv
#define BB 4
#define OC 18      // offset channels actually used
#define OCP 20     // padded (10 f32x2 pairs, 16B-aligned rows)
#define HW (HH*WW)

typedef unsigned long long ull;

// ---------------------------------------------------------------------------
// f32x2 packed helpers (sm_103a FFMA2 path — only reachable via PTX)
// ---------------------------------------------------------------------------
__device__ __forceinline__ void ffma2(ull& d, ull a, ull b) {
    asm("fma.rn.f32x2 %0, %1, %2, %0;" : "+l"(d) : "l"(a), "l"(b));
}
__device__ __forceinline__ ull packf(float lo, float hi) {
    ull r; asm("mov.b64 %0, {%1, %2};" : "=l"(r) : "f"(lo), "f"(hi)); return r;
}
__device__ __forceinline__ void unpackf(ull v, float& lo, float& hi) {
    asm("mov.b64 {%0, %1}, %2;" : "=f"(lo), "=f"(hi) : "l"(v));
}

// Deform weights packed as o-pairs: g_wdup[(k*64 + c)*32 + j] = {w[2j], w[2j+1]}
__device__ ull g_wdup[9 * CC * 32];

// ---------------------------------------------------------------------------
// Prelude: transpose + pair-pack dc_w (64,64,3,3) -> g_wdup[k][c][opair]
// ---------------------------------------------------------------------------
__global__ void wdup_kernel(const float* __restrict__ dw)
{
    int idx = blockIdx.x * blockDim.x + threadIdx.x;   // 0 .. 9*64*32-1
    int j = idx & 31;          // o-pair
    int c = (idx >> 5) & 63;
    int k = idx >> 11;
    float w0 = __ldg(dw + ((2 * j)     * CC + c) * 9 + k);
    float w1 = __ldg(dw + ((2 * j + 1) * CC + c) * 9 + k);
    g_wdup[idx] = packf(w0, w1);
}

// ---------------------------------------------------------------------------
// Kernel A: 3x3 conv (pad 1): blur x offset_w -> offset (18 ch).
// One thread per pixel; 10 f32x2 accumulators packed over o-pairs.
// Weight pairs in smem, read via ulonglong2 (LDS.128, no pack MOVs).
// ---------------------------------------------------------------------------
__global__ __launch_bounds__(256, 4)
void offset_conv_kernel(const float* __restrict__ blur,
                        const float* __restrict__ ow,   // (27,64,3,3)
                        const float* __restrict__ ob,   // (27,)
                        float* __restrict__ off_out)    // (4,18,256,256)
{
    __shared__ ull ws2[CC * 9 * (OCP / 2)];   // [c*9+k][opair], 46,080 B

    const int tid = threadIdx.x;
    for (int i = tid; i < CC * 9 * (OCP / 2); i += blockDim.x) {
        int j  = i % (OCP / 2);       // o-pair
        int ck = i / (OCP / 2);       // c*9 + k
        int o0 = 2 * j, o1 = 2 * j + 1;
        float w0 = (o0 < OC) ? ow[o0 * (CC * 9) + ck] : 0.0f;
        float w1 = (o1 < OC) ? ow[o1 * (CC * 9) + ck] : 0.0f;
        ws2[i] = packf(w0, w1);
    }
    __syncthreads();

    const int p = blockIdx.x * blockDim.x + tid;
    const int x = p & (WW - 1);
    const int y = (p >> 8) & (HH - 1);
    const int b = p >> 16;

    ull acc[OCP / 2];
#pragma unroll
    for (int j = 0; j < OCP / 2; j++) acc[j] = 0ull;

    const float* bp = blur + (size_t)b * CC * HW;

    for (int c = 0; c < CC; c++) {
        const float* cp = bp + c * HW;
#pragma unroll
        for (int k = 0; k < 9; k++) {
            const int iy = y + k / 3 - 1;
            const int ix = x + k % 3 - 1;
            float v = 0.0f;
            if (iy >= 0 && iy < HH && ix >= 0 && ix < WW)
                v = __ldg(cp + iy * WW + ix);
            const ull vv = packf(v, v);
            const ulonglong2* w2 = reinterpret_cast<const ulonglong2*>(
                ws2 + (c * 9 + k) * (OCP / 2));
#pragma unroll
            for (int j = 0; j < 5; j++) {
                ulonglong2 t = w2[j];
                ffma2(acc[2 * j],     t.x, vv);
                ffma2(acc[2 * j + 1], t.y, vv);
            }
        }
    }

    float* op = off_out + ((size_t)b * OC) * HW + y * WW + x;
#pragma unroll
    for (int j = 0; j < 9; j++) {       // pairs 0..8 cover o = 0..17
        float a0, a1;
        unpackf(acc[j], a0, a1);
        op[(2 * j)     * HW] = a0 + __ldg(ob + 2 * j);
        op[(2 * j + 1) * HW] = a1 + __ldg(ob + 2 * j + 1);
    }
}

// ---------------------------------------------------------------------------
// Kernel B: deformable conv. R2's proven interleaved structure (thread=pixel,
// gather fused with MAC, 16 warps hide gather latency), upgraded to:
//  - f32x2 o-pair accumulators (32 ull) + fma.rn.f32x2  -> FFMA issue halved
//  - weight pairs staged to smem from pre-packed g_wdup (coalesced staging)
//  - ulonglong2 smem reads (LDS.128 -> aligned reg pairs, no pack MOVs)
// ---------------------------------------------------------------------------
__global__ __launch_bounds__(256, 2)
void deform_conv_kernel(const float* __restrict__ content,
                        const float* __restrict__ offset,  // (4,18,256,256)
                        const float* __restrict__ db,      // (64,)
                        float* __restrict__ out)           // (4,64,256,256)
{
    __shared__ ull ws2[CC * 32];   // weight pairs for current k, 16 KB

    const int tid = threadIdx.x;
    const int p = blockIdx.x * blockDim.x + tid;
    const int x = p & (WW - 1);
    const int y = (p >> 8) & (HH - 1);
    const int b = p >> 16;

    ull acc[32];                   // o-pair accumulators (64 channels)
#pragma unroll
    for (int j = 0; j < 32; j++) acc[j] = 0ull;

    const float* cb   = content + (size_t)b * CC * HW;
    const float* offb = offset + (size_t)b * OC * HW + y * WW + x;

    for (int k = 0; k < 9; k++) {
        __syncthreads();
        // coalesced staging: 1024 x ulonglong2 (16 KB) from pre-packed layout
        {
            const ulonglong2* src =
                reinterpret_cast<const ulonglong2*>(g_wdup + (size_t)k * CC * 32);
            ulonglong2* dst = reinterpret_cast<ulonglong2*>(ws2);
            for (int i = tid; i < CC * 16; i += blockDim.x)
                dst[i] = __ldg(src + i);
        }
        __syncthreads();

        const float offy = __ldg(offb + (2 * k) * HW);
        const float offx = __ldg(offb + (2 * k + 1) * HW);
        const float py = (float)(y + (k / 3) - 1) + offy;
        const float px = (float)(x + (k % 3) - 1) + offx;

        const float y0f = floorf(py);
        const float x0f = floorf(px);
        const float wy = py - y0f;
        const float wx = px - x0f;
        const int iy0 = (int)y0f, ix0 = (int)x0f;
        const int iy1 = iy0 + 1,  ix1 = ix0 + 1;

        const bool vy0 = (iy0 >= 0) && (iy0 < HH);
        const bool vy1 = (iy1 >= 0) && (iy1 < HH);
        const bool vx0 = (ix0 >= 0) && (ix0 < WW);
        const bool vx1 = (ix1 >= 0) && (ix1 < WW);

        const float w00 = (1.f - wy) * (1.f - wx) * ((vy0 && vx0) ? 1.f : 0.f);
        const float w01 = (1.f - wy) * wx         * ((vy0 && vx1) ? 1.f : 0.f);
        const float w10 = wy * (1.f - wx)         * ((vy1 && vx0) ? 1.f : 0.f);
        const float w11 = wy * wx                 * ((vy1 && vx1) ? 1.f : 0.f);

        const int cy0 = min(max(iy0, 0), HH - 1);
        const int cy1 = min(max(iy1, 0), HH - 1);
        const int cx0 = min(max(ix0, 0), WW - 1);
        const int cx1 = min(max(ix1, 0), WW - 1);

        const float* p00 = cb + cy0 * WW + cx0;
        const float* p01 = cb + cy0 * WW + cx1;
        const float* p10 = cb + cy1 * WW + cx0;
        const float* p11 = cb + cy1 * WW + cx1;

#pragma unroll 2
        for (int c = 0; c < CC; c++) {
            const int co = c * HW;
            const float samp = w00 * __ldg(p00 + co)
                             + w01 * __ldg(p01 + co)
                             + w10 * __ldg(p10 + co)
                             + w11 * __ldg(p11 + co);
            const ull vv = packf(samp, samp);
            const ulonglong2* wp = reinterpret_cast<const ulonglong2*>(ws2 + c * 32);
#pragma unroll
            for (int j = 0; j < 16; j++) {
                ulonglong2 t = wp[j];
                ffma2(acc[2 * j],     t.x, vv);   // o-pair 2j   (o = 4j, 4j+1)
                ffma2(acc[2 * j + 1], t.y, vv);   // o-pair 2j+1 (o = 4j+2, 4j+3)
            }
        }
    }

    // epilogue: unpack 32 o-pairs -> 64 channels (+bias), coalesced stores
    float* op = out + (size_t)b * CC * HW + y * WW + x;
#pragma unroll
    for (int j = 0; j < 32; j++) {
        float a0, a1;
        unpackf(acc[j], a0, a1);
        op[(2 * j)     * HW] = a0 + __ldg(db + 2 * j);
        op[(2 * j + 1) * HW] = a1 + __ldg(db + 2 * j + 1);
    }
}

// ---------------------------------------------------------------------------
// kernel_launch
//   d_in[0] content_feats (4,64,256,256) f32
//   d_in[1] blur_feats    (4,64,256,256) f32
//   d_in[2] offset_w      (27,64,3,3)    f32
//   d_in[3] offset_b      (27,)          f32
//   d_in[4] dc_w          (64,64,3,3)    f32
//   d_in[5] dc_b          (64,)          f32
// d_out = [ out (4,64,256,256) | offset (4,18,256,256) ]
// ---------------------------------------------------------------------------
extern "C" void kernel_launch(void* const* d_in, const int* in_sizes, int n_in,
                              void* d_out, int out_size)
{
    const float* content = (const float*)d_in[0];
    const float* blur    = (const float*)d_in[1];
    const float* ow      = (const float*)d_in[2];
    const float* ob      = (const float*)d_in[3];
    const float* dw      = (const float*)d_in[4];
    const float* db      = (const float*)d_in[5];

    float* out     = (float*)d_out;
    float* off_out = out + (size_t)BB * CC * HW;

    wdup_kernel<<<(9 * CC * 32) / 256, 256>>>(dw);
    offset_conv_kernel<<<(BB * HW) / 256, 256>>>(blur, ow, ob, off_out);
    deform_conv_kernel<<<(BB * HW) / 256, 256>>>(content, off_out, db, out);
}

// round 8
// speedup vs baseline: 1.8509x; 1.2769x over previous
#include <cuda_runtime.h>

// Problem constants
#define HH 256
#define WW 256
#define CC 64      // content/blur channels, also output channels of deform conv
#define BB 4
#define OC 18      // offset channels actually used (9 o-pairs exactly)
#define HW (HH*WW)

typedef unsigned long long ull;

// ---------------------------------------------------------------------------
// f32x2 packed helpers (sm_103a FFMA2 path — only reachable via PTX)
// ---------------------------------------------------------------------------
__device__ __forceinline__ void ffma2(ull& d, ull a, ull b) {
    asm("fma.rn.f32x2 %0, %1, %2, %0;" : "+l"(d) : "l"(a), "l"(b));
}
__device__ __forceinline__ ull packf(float lo, float hi) {
    ull r; asm("mov.b64 %0, {%1, %2};" : "=l"(r) : "f"(lo), "f"(hi)); return r;
}
__device__ __forceinline__ void unpackf(ull v, float& lo, float& hi) {
    asm("mov.b64 {%0, %1}, %2;" : "=f"(lo), "=f"(hi) : "l"(v));
}

// Constant weight bank (49,152 B) — reloaded between launches via async D2D
// memcpy-to-symbol nodes. Warp-uniform reads -> ULDC/LDCU (uniform port,
// off the l1tex pipe).
__constant__ ull c_wpair[3 * CC * 32];     // deform: [kk][c][o-pair]

// Staging buffers in global (filled by pack kernels, copied to c_wpair)
__device__ ull g_wdup[9 * CC * 32];        // deform pairs [k][c][j]
__device__ ull g_owpair[CC * 9 * (OC/2)];  // offset-conv pairs [c*9+k][j]

// ---------------------------------------------------------------------------
// Prelude packers
// ---------------------------------------------------------------------------
__global__ void wdup_kernel(const float* __restrict__ dw)
{
    int idx = blockIdx.x * blockDim.x + threadIdx.x;   // 0 .. 9*64*32-1
    int j = idx & 31;          // o-pair
    int c = (idx >> 5) & 63;
    int k = idx >> 11;
    float w0 = __ldg(dw + ((2 * j)     * CC + c) * 9 + k);
    float w1 = __ldg(dw + ((2 * j + 1) * CC + c) * 9 + k);
    g_wdup[idx] = packf(w0, w1);
}

__global__ void owpack_kernel(const float* __restrict__ ow)  // (27,64,3,3)
{
    int idx = blockIdx.x * blockDim.x + threadIdx.x;   // 0 .. 576*9-1
    if (idx >= CC * 9 * (OC / 2)) return;
    int j  = idx % (OC / 2);
    int ck = idx / (OC / 2);         // c*9 + k
    float w0 = __ldg(ow + (2 * j)     * (CC * 9) + ck);
    float w1 = __ldg(ow + (2 * j + 1) * (CC * 9) + ck);
    g_owpair[idx] = packf(w0, w1);
}

// ---------------------------------------------------------------------------
// Kernel A: 3x3 conv (pad 1): blur x offset_w -> offset (18 ch).
// One thread per pixel; 9 f32x2 o-pair accumulators. Weights from the
// constant bank (first 5184 entries) -> uniform-port loads, no smem.
// ---------------------------------------------------------------------------
__global__ __launch_bounds__(256, 4)
void offset_conv_kernel(const float* __restrict__ blur,
                        const float* __restrict__ ob,   // (27,)
                        float* __restrict__ off_out)    // (4,18,256,256)
{
    const int tid = threadIdx.x;
    const int p = blockIdx.x * blockDim.x + tid;
    const int x = p & (WW - 1);
    const int y = (p >> 8) & (HH - 1);
    const int b = p >> 16;

    ull acc[OC / 2];
#pragma unroll
    for (int j = 0; j < OC / 2; j++) acc[j] = 0ull;

    const float* bp = blur + (size_t)b * CC * HW;

    for (int c = 0; c < CC; c++) {
        const float* cp = bp + c * HW;
#pragma unroll
        for (int k = 0; k < 9; k++) {
            const int iy = y + k / 3 - 1;
            const int ix = x + k % 3 - 1;
            float v = 0.0f;
            if (iy >= 0 && iy < HH && ix >= 0 && ix < WW)
                v = __ldg(cp + iy * WW + ix);
            const ull vv = packf(v, v);
            const ull* wp = c_wpair + (c * 9 + k) * (OC / 2);
#pragma unroll
            for (int j = 0; j < OC / 2; j++)
                ffma2(acc[j], wp[j], vv);
        }
    }

    float* op = off_out + ((size_t)b * OC) * HW + y * WW + x;
#pragma unroll
    for (int j = 0; j < OC / 2; j++) {
        float a0, a1;
        unpackf(acc[j], a0, a1);
        op[(2 * j)     * HW] = a0 + __ldg(ob + 2 * j);
        op[(2 * j + 1) * HW] = a1 + __ldg(ob + 2 * j + 1);
    }
}

// ---------------------------------------------------------------------------
// Kernel B: deformable conv, 3 taps per launch. Thread = pixel, interleaved
// gather + MAC (R2/R7 proven structure). Weights come from c_wpair (uniform
// constant port) so l1tex carries ONLY the bilinear gathers.
// first=1: write acc+bias; else: accumulate into existing out.
// ---------------------------------------------------------------------------
__global__ __launch_bounds__(256, 2)
void deform_group_kernel(const float* __restrict__ content,
                         const float* __restrict__ offset,  // (4,18,256,256)
                         const float* __restrict__ db,      // (64,)
                         float* __restrict__ out,           // (4,64,256,256)
                         int k0, int first)
{
    const int tid = threadIdx.x;
    const int p = blockIdx.x * blockDim.x + tid;
    const int x = p & (WW - 1);
    const int y = (p >> 8) & (HH - 1);
    const int b = p >> 16;

    ull acc[32];                   // o-pair accumulators (64 channels)
#pragma unroll
    for (int j = 0; j < 32; j++) acc[j] = 0ull;

    const float* cb   = content + (size_t)b * CC * HW;
    const float* offb = offset + (size_t)b * OC * HW + y * WW + x;

#pragma unroll
    for (int kk = 0; kk < 3; kk++) {
        const int k = k0 + kk;

        const float offy = __ldg(offb + (2 * k) * HW);
        const float offx = __ldg(offb + (2 * k + 1) * HW);
        const float py = (float)(y + (k / 3) - 1) + offy;
        const float px = (float)(x + (k % 3) - 1) + offx;

        const float y0f = floorf(py);
        const float x0f = floorf(px);
        const float wy = py - y0f;
        const float wx = px - x0f;
        const int iy0 = (int)y0f, ix0 = (int)x0f;
        const int iy1 = iy0 + 1,  ix1 = ix0 + 1;

        const bool vy0 = (iy0 >= 0) && (iy0 < HH);
        const bool vy1 = (iy1 >= 0) && (iy1 < HH);
        const bool vx0 = (ix0 >= 0) && (ix0 < WW);
        const bool vx1 = (ix1 >= 0) && (ix1 < WW);

        const float w00 = (1.f - wy) * (1.f - wx) * ((vy0 && vx0) ? 1.f : 0.f);
        const float w01 = (1.f - wy) * wx         * ((vy0 && vx1) ? 1.f : 0.f);
        const float w10 = wy * (1.f - wx)         * ((vy1 && vx0) ? 1.f : 0.f);
        const float w11 = wy * wx                 * ((vy1 && vx1) ? 1.f : 0.f);

        const int cy0 = min(max(iy0, 0), HH - 1);
        const int cy1 = min(max(iy1, 0), HH - 1);
        const int cx0 = min(max(ix0, 0), WW - 1);
        const int cx1 = min(max(ix1, 0), WW - 1);

        const float* p00 = cb + cy0 * WW + cx0;
        const float* p01 = cb + cy0 * WW + cx1;
        const float* p10 = cb + cy1 * WW + cx0;
        const float* p11 = cb + cy1 * WW + cx1;

        const ull* wbank = c_wpair + kk * (CC * 32);

#pragma unroll 2
        for (int c = 0; c < CC; c++) {
            const int co = c * HW;
            const float samp = w00 * __ldg(p00 + co)
                             + w01 * __ldg(p01 + co)
                             + w10 * __ldg(p10 + co)
                             + w11 * __ldg(p11 + co);
            const ull vv = packf(samp, samp);
            const ull* wp = wbank + c * 32;
#pragma unroll
            for (int j = 0; j < 32; j++)
                ffma2(acc[j], wp[j], vv);
        }
    }

    // epilogue: unpack 32 o-pairs -> 64 channels, coalesced
    float* op = out + (size_t)b * CC * HW + y * WW + x;
    if (first) {
#pragma unroll
        for (int j = 0; j < 32; j++) {
            float a0, a1;
            unpackf(acc[j], a0, a1);
            op[(2 * j)     * HW] = a0 + __ldg(db + 2 * j);
            op[(2 * j + 1) * HW] = a1 + __ldg(db + 2 * j + 1);
        }
    } else {
#pragma unroll
        for (int j = 0; j < 32; j++) {
            float a0, a1;
            unpackf(acc[j], a0, a1);
            op[(2 * j)     * HW] += a0;
            op[(2 * j + 1) * HW] += a1;
        }
    }
}

// ---------------------------------------------------------------------------
// kernel_launch
//   d_in[0] content_feats (4,64,256,256) f32
//   d_in[1] blur_feats    (4,64,256,256) f32
//   d_in[2] offset_w      (27,64,3,3)    f32
//   d_in[3] offset_b      (27,)          f32
//   d_in[4] dc_w          (64,64,3,3)    f32
//   d_in[5] dc_b          (64,)          f32
// d_out = [ out (4,64,256,256) | offset (4,18,256,256) ]
// ---------------------------------------------------------------------------
extern "C" void kernel_launch(void* const* d_in, const int* in_sizes, int n_in,
                              void* d_out, int out_size)
{
    const float* content = (const float*)d_in[0];
    const float* blur    = (const float*)d_in[1];
    const float* ow      = (const float*)d_in[2];
    const float* ob      = (const float*)d_in[3];
    const float* dw      = (const float*)d_in[4];
    const float* db      = (const float*)d_in[5];

    float* out     = (float*)d_out;
    float* off_out = out + (size_t)BB * CC * HW;

    // staging addresses of the pack buffers (no allocation)
    void* wdup_addr = nullptr;
    void* owp_addr  = nullptr;
    cudaGetSymbolAddress(&wdup_addr, g_wdup);
    cudaGetSymbolAddress(&owp_addr,  g_owpair);
    const ull* wdup_p = (const ull*)wdup_addr;

    // 1) pack weights into pair layouts
    wdup_kernel<<<(9 * CC * 32) / 256, 256>>>(dw);
    owpack_kernel<<<(CC * 9 * (OC / 2) + 255) / 256, 256>>>(ow);

    // 2) offset conv (weights via constant bank)
    cudaMemcpyToSymbolAsync(c_wpair, owp_addr,
                            (size_t)CC * 9 * (OC / 2) * sizeof(ull), 0,
                            cudaMemcpyDeviceToDevice, 0);
    offset_conv_kernel<<<(BB * HW) / 256, 256>>>(blur, ob, off_out);

    // 3) deform conv in 3 tap-groups, constant bank reloaded per group
    const size_t grp_bytes = (size_t)3 * CC * 32 * sizeof(ull);   // 49,152
    for (int g = 0; g < 3; g++) {
        cudaMemcpyToSymbolAsync(c_wpair, wdup_p + (size_t)g * 3 * CC * 32,
                                grp_bytes, 0, cudaMemcpyDeviceToDevice, 0);
        deform_group_kernel<<<(BB * HW) / 256, 256>>>(
            content, off_out, db, out, 3 * g, g == 0 ? 1 : 0);
    }
}